// round 16
// baseline (speedup 1.0000x reference)
#include <cuda_runtime.h>
#include <cuda_bf16.h>

#define PP     76800     // H*W
#define HH     240
#define WW     320
#define NC     22        // classes
#define NR     6         // u64 groups of 4 u16 class lanes
#define NQ     300       // query points (15*20)
#define QW     20
#define QH     15
#define QSKIP  16
#define EPSF   1e-6f
#define C1F    (0.9f * 1e-6f)

#define THR    640       // 2 query-range copies of the row's 320 pixels
#define NW     10        // pixel-warp mask slots per query
#define NWP    11        // padded mask row stride (coprime with 32)
#define BLKS   240       // 1 image row per block; 2 blocks/SM => co-resident

typedef unsigned long long ull;

// ---------------- device scratch (zero-init; reset by last block each launch) -
__device__ ull   g_accP[NQ * NR];
__device__ int   g_clsCnt[NC];
__device__ float g_zsum[NC];
__device__ int   g_phase1;
__device__ int   g_phase2;

// Exact inlier bit — byte-identical op sequence to rounds 4..15.
__device__ __forceinline__ unsigned ibit(float cx, float cy, float ux, float uy,
                                         float K) {
    float s   = cx * cx;
    float rhs = fmaf(s, 0.81f, K);
    float w   = fmaf(cy, uy, -C1F);
    float tv  = fmaf(cx, ux, w);
    float tt  = tv * fabsf(tv);
    float d   = fmaf(tt, -1.0f, rhs);
    return __float_as_uint(d) >> 31;
}

// =============== single persistent kernel ====================================
__global__ void __launch_bounds__(THR, 2) k_all(const int* __restrict__ label,
                                                const float* __restrict__ vp,
                                                const float* __restrict__ extents,
                                                const float* __restrict__ poses,
                                                const float* __restrict__ mdata,
                                                float* __restrict__ out) {
    __shared__ union {
        unsigned int masks[NQ * NWP];  // 13.2 KB inlier masks [q][pixel-warp]
        ull          tab[NQ * NR];     // 14.4 KB staged vote table (phase 2)
    } sB;
    __shared__ unsigned int sClsm[NW * NC];   // per-pixel-warp class masks
    __shared__ int   sCC[NC];
    __shared__ int   sBQ[NC];
    __shared__ float sBV[NC];
    __shared__ float sZ[NC];
    __shared__ int   sLast;

    int t    = threadIdx.x;
    int lane = t & 31;
    int wid  = t >> 5;
    int row  = blockIdx.x;

    if (t < NC) { sCC[t] = 0; sZ[t] = 0.0f; }
    if (t == 0) sLast = 0;

    // ---------------- prep: pixel in registers (both copies load same row) ---
    int copy = (t >= WW);
    int px   = t - copy * WW;                   // pixel column
    int p    = row * WW + px;
    int lab  = label[p];
    float ux = 0.0f, uy = 0.0f, dz = 0.0f;
    if (lab > 0) {
        float dx = vp[(3 * lab + 0) * PP + p];
        float dy = vp[(3 * lab + 1) * PP + p];
        dz       = vp[(3 * lab + 2) * PP + p];
        float dn = sqrtf(dx * dx + dy * dy) + EPSF;
        ux = dx / dn;
        uy = dy / dn;
    }
    if (t < WW) {                               // count each pixel once
        unsigned m = __match_any_sync(0xffffffffu, lab);
        if (lane == __ffs(m) - 1) atomicAdd(&sCC[lab], __popc(m));
        #pragma unroll
        for (int c = 0; c < NC; c++) {          // per-warp class masks (once)
            unsigned mm = __ballot_sync(0xffffffffu, lab == c);
            if (lane == c) sClsm[wid * NC + c] = mm;
        }
    }
    __syncthreads();

    // ---------------- vote: register bit-accumulate + warp bit-transpose -----
    // copy 0: query groups 0..4 (q 0..159); copy 1: groups 5..9 (q 160..299).
    // No VOTE in hot loop; OR chain split in halves. FP sequence == ibit.
    {
        int ws   = wid - copy * NW;                   // mask slot 0..9
        int g0   = copy ? 5 : 0;
        int g1   = copy ? 10 : 5;
        float fpx  = (float)px;
        float frow = (float)row;
        unsigned int* __restrict__ mk = sB.masks;
        #pragma unroll 1
        for (int g = g0; g < g1; g++) {
            unsigned blo = 0, bhi = 0;                // split OR chains
            #pragma unroll
            for (int k = 0; k < 32; k++) {
                const int q = g * 32 + k;
                if (q < NQ) {
                    const int r = q / QW;
                    const int i = q - r * QW;
                    float cy  = (float)(r * QSKIP) - frow;   // exact small ints
                    float K   = (0.81f * cy) * cy;           // CSE'd per row
                    float w   = fmaf(cy, uy, -C1F);          // CSE'd per row
                    float cx  = (float)(i * QSKIP) - fpx;    // exact small ints
                    float s   = cx * cx;
                    float rhs = fmaf(s, 0.81f, K);
                    float tv  = fmaf(cx, ux, w);
                    float tt  = tv * fabsf(tv);
                    float d   = fmaf(tt, -1.0f, rhs);
                    unsigned b = __float_as_uint(d) >> 31;
                    if (k < 16) blo |= (b << k);
                    else        bhi |= (b << (k - 16));
                }
            }
            unsigned x = blo | (bhi << 16), pr;
            // 32x32 bit-matrix transpose across the warp (block-swap network)
            pr = __shfl_xor_sync(0xffffffffu, x, 16);
            x = (lane & 16) ? ((x & 0xFFFF0000u) | ((pr & 0xFFFF0000u) >> 16))
                            : ((x & 0x0000FFFFu) | ((pr & 0x0000FFFFu) << 16));
            pr = __shfl_xor_sync(0xffffffffu, x, 8);
            x = (lane & 8)  ? ((x & 0xFF00FF00u) | ((pr & 0xFF00FF00u) >> 8))
                            : ((x & 0x00FF00FFu) | ((pr & 0x00FF00FFu) << 8));
            pr = __shfl_xor_sync(0xffffffffu, x, 4);
            x = (lane & 4)  ? ((x & 0xF0F0F0F0u) | ((pr & 0xF0F0F0F0u) >> 4))
                            : ((x & 0x0F0F0F0Fu) | ((pr & 0x0F0F0F0Fu) << 4));
            pr = __shfl_xor_sync(0xffffffffu, x, 2);
            x = (lane & 2)  ? ((x & 0xCCCCCCCCu) | ((pr & 0xCCCCCCCCu) >> 2))
                            : ((x & 0x33333333u) | ((pr & 0x33333333u) << 2));
            pr = __shfl_xor_sync(0xffffffffu, x, 1);
            x = (lane & 1)  ? ((x & 0xAAAAAAAAu) | ((pr & 0xAAAAAAAAu) >> 1))
                            : ((x & 0x55555555u) | ((pr & 0x55555555u) << 1));
            int q = g * 32 + lane;
            if (q < NQ) mk[q * NWP + ws] = x;   // conflict-free (stride 11)
        }
    }
    __syncthreads();

    // ---------------- merge: per-query popc against class masks --------------
    if (t < NQ) {
        unsigned cnt[NC];
        #pragma unroll
        for (int c = 0; c < NC; c++) cnt[c] = 0;
        #pragma unroll
        for (int w = 0; w < NW; w++) {
            unsigned m = sB.masks[t * NWP + w];
            if (m) {
                const unsigned* cm = &sClsm[w * NC];      // broadcast LDS
                #pragma unroll
                for (int c = 1; c < NC; c++)
                    cnt[c] += __popc(m & cm[c]);
            }
        }
        // pack 4 u16 lanes per u64, 6 REDs per query (exact integer sums)
        #pragma unroll
        for (int g = 0; g < NR; g++) {
            int c0 = 4 * g;
            ull v = (ull)cnt[c0];
            if (c0 + 1 < NC) v |= (ull)cnt[c0 + 1] << 16;
            if (c0 + 2 < NC) v |= (ull)cnt[c0 + 2] << 32;
            if (c0 + 3 < NC) v |= (ull)cnt[c0 + 3] << 48;
            if (v) atomicAdd(&g_accP[t * NR + g], v);
        }
    }
    if (t < NC && sCC[t]) atomicAdd(&g_clsCnt[t], sCC[t]);

    // ---------------- grid barrier (2 blocks/SM enforced => co-resident) -----
    __threadfence();
    __syncthreads();
    if (t == 0) {
        atomicAdd(&g_phase1, 1);
        while (atomicAdd(&g_phase1, 0) < BLKS) __nanosleep(64);
    }
    __syncthreads();

    // ---------------- phase 2: stage table (overwrites masks) ----------------
    for (int i = t; i < NQ * NR; i += THR) sB.tab[i] = __ldcg(&g_accP[i]);
    __syncthreads();

    // per-class argmax on u16 lanes, integer compare (first-index ties)
    {
        int w = t >> 5;                          // 20 warps
        for (int c = w; c < NC; c += 20) {
            int g  = c >> 2;
            int sh = (c & 3) * 16;
            int best = -1, bq = 0;
            for (int q = lane; q < NQ; q += 32) {
                int v = (int)((sB.tab[q * NR + g] >> sh) & 0xFFFFu);
                if (v > best) { best = v; bq = q; }
            }
            #pragma unroll
            for (int off = 16; off; off >>= 1) {
                int ov = __shfl_down_sync(0xffffffffu, best, off);
                int oq = __shfl_down_sync(0xffffffffu, bq,   off);
                if (ov > best || (ov == best && oq < bq)) { best = ov; bq = oq; }
            }
            if (lane == 0) { sBQ[c] = bq; sBV[c] = (float)best; }
        }
    }
    __syncthreads();

    // z-sum: each pixel once (t < 320); registers survived the barrier
    if (t < WW && lab > 0) {
        int q = sBQ[lab];
        float qx = (float)((q % QW) * QSKIP);
        float qy = (float)((q / QW) * QSKIP);
        float cy = qy - (float)row;
        float K  = (0.81f * cy) * cy;
        float cx = qx - (float)px;
        if (ibit(cx, cy, ux, uy, K))             // same rounding as vote
            atomicAdd(&sZ[lab], dz);
    }
    __syncthreads();
    if (t < NC && sZ[t] != 0.0f) atomicAdd(&g_zsum[t], sZ[t]);
    __threadfence();
    __syncthreads();
    if (t == 0) {
        if (atomicAdd(&g_phase2, 1) == BLKS - 1) sLast = 1;
    }
    __syncthreads();
    if (!sLast) return;

    // ================= last block: assemble output + reset scratch ===========
    if (t < NC) {
        int c = t;
        float fx  = mdata[0] + EPSF;
        float fy  = mdata[4] + EPSF;
        float ppx = mdata[2];
        float ppy = mdata[5];

        float bv = sBV[c];
        int   bq = sBQ[c];
        float bx = (float)((bq % QW) * QSKIP);
        float by = (float)((bq / QW) * QSKIP);

        float cc = (float)__ldcg(&g_clsCnt[c]);
        float z  = __ldcg(&g_zsum[c]) / (bv + EPSF);   // cnt == best_votes

        float ex = extents[c * 3 + 0];
        float ey = extents[c * 3 + 1];
        float ez = extents[c * 3 + 2];
        float half = 0.5f * sqrtf(ex * ex + ey * ey + ez * ez);

        float zsafe = (fabsf(z) > EPSF) ? z : EPSF;
        float r = fx * half / zsafe;

        bool valid = (bv >= 50.0f) && (cc >= 500.0f) && (bv / (cc + EPSF) >= 0.02f);
        float score = valid ? bv : 0.0f;

        float* o = out + c * 14;
        o[0]  = 0.0f;
        o[1]  = (float)c;
        o[2]  = bx - r;
        o[3]  = by - r;
        o[4]  = bx + r;
        o[5]  = by + r;
        o[6]  = score;
        o[7]  = poses[c * 13 + 6];
        o[8]  = poses[c * 13 + 7];
        o[9]  = poses[c * 13 + 8];
        o[10] = poses[c * 13 + 9];
        o[11] = (bx - ppx) * z / fx;
        o[12] = (by - ppy) * z / fy;
        o[13] = z;

        g_clsCnt[c] = 0;                 // reset for next graph replay
        g_zsum[c]   = 0.0f;
    }
    for (int i = t; i < NQ * NR; i += THR) g_accP[i] = 0ULL;
    __threadfence();
    if (t == 0) { g_phase1 = 0; g_phase2 = 0; }
}

// ---------------- launch ------------------------------------------------------
extern "C" void kernel_launch(void* const* d_in, const int* in_sizes, int n_in,
                              void* d_out, int out_size) {
    const int*   label   = (const int*)  d_in[0];   // (1,240,320) int32
    const float* vp      = (const float*)d_in[1];   // (1,66,240,320) f32
    const float* extents = (const float*)d_in[2];   // (22,3) f32
    const float* poses   = (const float*)d_in[3];   // (22,13) f32
    const float* mdata   = (const float*)d_in[4];   // (1,9) f32
    float*       out     = (float*)d_out;           // (1,22,14) f32

    k_all<<<BLKS, THR>>>(label, vp, extents, poses, mdata, out);
}

// round 17
// speedup vs baseline: 1.6689x; 1.6689x over previous
#include <cuda_runtime.h>
#include <cuda_bf16.h>

#define PP     76800     // H*W
#define HH     240
#define WW     320
#define NC     22        // classes
#define NR     6         // u64 groups of 4 u16 class lanes
#define NQ     300       // query points (15*20)
#define QW     20
#define QH     15
#define QSKIP  16
#define EPSF   1e-6f
#define C1F    (0.9f * 1e-6f)

#define THR    640       // 2 query-range copies of the row's 320 pixels
#define NW     10        // pixel-warp mask slots per query
#define NWP    11        // padded mask row stride (coprime with 32)
#define BLKS   240       // 1 image row per block; 2 blocks/SM => co-resident

typedef unsigned long long ull;

// ---------------- device scratch (zero-init; reset by last block each launch) -
__device__ ull   g_accP[NQ * NR];
__device__ int   g_clsCnt[NC];
__device__ float g_zsum[NC];
__device__ int   g_phase1;
__device__ int   g_phase2;

// Exact inlier bit — byte-identical op sequence to rounds 4..16.
__device__ __forceinline__ unsigned ibit(float cx, float cy, float ux, float uy,
                                         float K) {
    float s   = cx * cx;
    float rhs = fmaf(s, 0.81f, K);
    float w   = fmaf(cy, uy, -C1F);
    float tv  = fmaf(cx, ux, w);
    float tt  = tv * fabsf(tv);
    float d   = fmaf(tt, -1.0f, rhs);
    return __float_as_uint(d) >> 31;
}

// One 32-query group: compile-time G => q/r/i constants fold to immediates,
// per-row cy/K/w CSE'd by the compiler. FP sequence == ibit -> identical bits.
template<int G>
__device__ __forceinline__ void vote_group(float ux, float uy, float fpx,
                                           float frow, int lane, int ws,
                                           unsigned int* __restrict__ mk) {
    unsigned blo = 0, bhi = 0;                 // split OR chains
    #pragma unroll
    for (int k = 0; k < 32; k++) {
        const int q = G * 32 + k;
        if (q < NQ) {
            const int r = q / QW;              // compile-time
            const int i = q - r * QW;          // compile-time
            float cy  = (float)(r * QSKIP) - frow;   // immediate FADD
            float K   = (0.81f * cy) * cy;           // CSE'd per row
            float w   = fmaf(cy, uy, -C1F);          // CSE'd per row
            float cx  = (float)(i * QSKIP) - fpx;    // immediate FADD
            float s   = cx * cx;
            float rhs = fmaf(s, 0.81f, K);
            float tv  = fmaf(cx, ux, w);
            float tt  = tv * fabsf(tv);
            float d   = fmaf(tt, -1.0f, rhs);
            unsigned b = __float_as_uint(d) >> 31;
            if (k < 16) blo |= (b << k);
            else        bhi |= (b << (k - 16));
        }
    }
    unsigned x = blo | (bhi << 16), pr;
    // 32x32 bit-matrix transpose across the warp (block-swap network)
    pr = __shfl_xor_sync(0xffffffffu, x, 16);
    x = (lane & 16) ? ((x & 0xFFFF0000u) | ((pr & 0xFFFF0000u) >> 16))
                    : ((x & 0x0000FFFFu) | ((pr & 0x0000FFFFu) << 16));
    pr = __shfl_xor_sync(0xffffffffu, x, 8);
    x = (lane & 8)  ? ((x & 0xFF00FF00u) | ((pr & 0xFF00FF00u) >> 8))
                    : ((x & 0x00FF00FFu) | ((pr & 0x00FF00FFu) << 8));
    pr = __shfl_xor_sync(0xffffffffu, x, 4);
    x = (lane & 4)  ? ((x & 0xF0F0F0F0u) | ((pr & 0xF0F0F0F0u) >> 4))
                    : ((x & 0x0F0F0F0Fu) | ((pr & 0x0F0F0F0Fu) << 4));
    pr = __shfl_xor_sync(0xffffffffu, x, 2);
    x = (lane & 2)  ? ((x & 0xCCCCCCCCu) | ((pr & 0xCCCCCCCCu) >> 2))
                    : ((x & 0x33333333u) | ((pr & 0x33333333u) << 2));
    pr = __shfl_xor_sync(0xffffffffu, x, 1);
    x = (lane & 1)  ? ((x & 0xAAAAAAAAu) | ((pr & 0xAAAAAAAAu) >> 1))
                    : ((x & 0x55555555u) | ((pr & 0x55555555u) << 1));
    int q = G * 32 + lane;
    if (q < NQ) mk[q * NWP + ws] = x;          // conflict-free (stride 11)
}

// =============== single persistent kernel ====================================
__global__ void __launch_bounds__(THR, 2) k_all(const int* __restrict__ label,
                                                const float* __restrict__ vp,
                                                const float* __restrict__ extents,
                                                const float* __restrict__ poses,
                                                const float* __restrict__ mdata,
                                                float* __restrict__ out) {
    __shared__ union {
        unsigned int masks[NQ * NWP];  // 13.2 KB inlier masks [q][pixel-warp]
        ull          tab[NQ * NR];     // 14.4 KB staged vote table (phase 2)
    } sB;
    __shared__ unsigned int sClsm[NW * NC];   // per-pixel-warp class masks
    __shared__ int   sCC[NC];
    __shared__ int   sBQ[NC];
    __shared__ float sBV[NC];
    __shared__ float sZ[NC];
    __shared__ int   sLast;

    int t    = threadIdx.x;
    int lane = t & 31;
    int wid  = t >> 5;
    int row  = blockIdx.x;

    if (t < NC) { sCC[t] = 0; sZ[t] = 0.0f; }
    if (t == 0) sLast = 0;

    // ---------------- prep: pixel in registers (both copies load same row) ---
    int copy = (t >= WW);
    int px   = t - copy * WW;                   // pixel column
    int p    = row * WW + px;
    int lab  = label[p];
    float ux = 0.0f, uy = 0.0f, dz = 0.0f;
    if (lab > 0) {
        float dx = vp[(3 * lab + 0) * PP + p];
        float dy = vp[(3 * lab + 1) * PP + p];
        dz       = vp[(3 * lab + 2) * PP + p];
        float dn = sqrtf(dx * dx + dy * dy) + EPSF;
        ux = dx / dn;
        uy = dy / dn;
    }
    if (t < WW) {                               // count each pixel once
        unsigned m = __match_any_sync(0xffffffffu, lab);
        if (lane == __ffs(m) - 1) atomicAdd(&sCC[lab], __popc(m));
        #pragma unroll
        for (int c = 0; c < NC; c++) {          // per-warp class masks (once)
            unsigned mm = __ballot_sync(0xffffffffu, lab == c);
            if (lane == c) sClsm[wid * NC + c] = mm;
        }
    }
    __syncthreads();

    // ---------------- vote: compile-time groups; copy 0: 0-4, copy 1: 5-9 ----
    {
        int ws     = wid - copy * NW;           // mask slot 0..9
        float fpx  = (float)px;
        float frow = (float)row;
        unsigned int* __restrict__ mk = sB.masks;
        if (copy == 0) {
            vote_group<0>(ux, uy, fpx, frow, lane, ws, mk);
            vote_group<1>(ux, uy, fpx, frow, lane, ws, mk);
            vote_group<2>(ux, uy, fpx, frow, lane, ws, mk);
            vote_group<3>(ux, uy, fpx, frow, lane, ws, mk);
            vote_group<4>(ux, uy, fpx, frow, lane, ws, mk);
        } else {
            vote_group<5>(ux, uy, fpx, frow, lane, ws, mk);
            vote_group<6>(ux, uy, fpx, frow, lane, ws, mk);
            vote_group<7>(ux, uy, fpx, frow, lane, ws, mk);
            vote_group<8>(ux, uy, fpx, frow, lane, ws, mk);
            vote_group<9>(ux, uy, fpx, frow, lane, ws, mk);
        }
    }
    __syncthreads();

    // ---------------- merge: per-query popc against class masks --------------
    if (t < NQ) {
        unsigned cnt[NC];
        #pragma unroll
        for (int c = 0; c < NC; c++) cnt[c] = 0;
        #pragma unroll
        for (int w = 0; w < NW; w++) {
            unsigned m = sB.masks[t * NWP + w];
            if (m) {
                const unsigned* cm = &sClsm[w * NC];      // broadcast LDS
                #pragma unroll
                for (int c = 1; c < NC; c++)
                    cnt[c] += __popc(m & cm[c]);
            }
        }
        // pack 4 u16 lanes per u64, 6 REDs per query (exact integer sums)
        #pragma unroll
        for (int g = 0; g < NR; g++) {
            int c0 = 4 * g;
            ull v = (ull)cnt[c0];
            if (c0 + 1 < NC) v |= (ull)cnt[c0 + 1] << 16;
            if (c0 + 2 < NC) v |= (ull)cnt[c0 + 2] << 32;
            if (c0 + 3 < NC) v |= (ull)cnt[c0 + 3] << 48;
            if (v) atomicAdd(&g_accP[t * NR + g], v);
        }
    }
    if (t < NC && sCC[t]) atomicAdd(&g_clsCnt[t], sCC[t]);

    // ---------------- grid barrier (2 blocks/SM enforced => co-resident) -----
    __threadfence();
    __syncthreads();
    if (t == 0) {
        atomicAdd(&g_phase1, 1);
        while (atomicAdd(&g_phase1, 0) < BLKS) __nanosleep(64);
    }
    __syncthreads();

    // ---------------- phase 2: stage table (overwrites masks) ----------------
    for (int i = t; i < NQ * NR; i += THR) sB.tab[i] = __ldcg(&g_accP[i]);
    __syncthreads();

    // per-class argmax on u16 lanes, integer compare (first-index ties)
    {
        int w = t >> 5;                          // 20 warps
        for (int c = w; c < NC; c += 20) {
            int g  = c >> 2;
            int sh = (c & 3) * 16;
            int best = -1, bq = 0;
            for (int q = lane; q < NQ; q += 32) {
                int v = (int)((sB.tab[q * NR + g] >> sh) & 0xFFFFu);
                if (v > best) { best = v; bq = q; }
            }
            #pragma unroll
            for (int off = 16; off; off >>= 1) {
                int ov = __shfl_down_sync(0xffffffffu, best, off);
                int oq = __shfl_down_sync(0xffffffffu, bq,   off);
                if (ov > best || (ov == best && oq < bq)) { best = ov; bq = oq; }
            }
            if (lane == 0) { sBQ[c] = bq; sBV[c] = (float)best; }
        }
    }
    __syncthreads();

    // z-sum: each pixel once (t < 320); registers survived the barrier
    if (t < WW && lab > 0) {
        int q = sBQ[lab];
        float qx = (float)((q % QW) * QSKIP);
        float qy = (float)((q / QW) * QSKIP);
        float cy = qy - (float)row;
        float K  = (0.81f * cy) * cy;
        float cx = qx - (float)px;
        if (ibit(cx, cy, ux, uy, K))             // same rounding as vote
            atomicAdd(&sZ[lab], dz);
    }
    __syncthreads();
    if (t < NC && sZ[t] != 0.0f) atomicAdd(&g_zsum[t], sZ[t]);
    __threadfence();
    __syncthreads();
    if (t == 0) {
        if (atomicAdd(&g_phase2, 1) == BLKS - 1) sLast = 1;
    }
    __syncthreads();
    if (!sLast) return;

    // ================= last block: assemble output + reset scratch ===========
    if (t < NC) {
        int c = t;
        float fx  = mdata[0] + EPSF;
        float fy  = mdata[4] + EPSF;
        float ppx = mdata[2];
        float ppy = mdata[5];

        float bv = sBV[c];
        int   bq = sBQ[c];
        float bx = (float)((bq % QW) * QSKIP);
        float by = (float)((bq / QW) * QSKIP);

        float cc = (float)__ldcg(&g_clsCnt[c]);
        float z  = __ldcg(&g_zsum[c]) / (bv + EPSF);   // cnt == best_votes

        float ex = extents[c * 3 + 0];
        float ey = extents[c * 3 + 1];
        float ez = extents[c * 3 + 2];
        float half = 0.5f * sqrtf(ex * ex + ey * ey + ez * ez);

        float zsafe = (fabsf(z) > EPSF) ? z : EPSF;
        float r = fx * half / zsafe;

        bool valid = (bv >= 50.0f) && (cc >= 500.0f) && (bv / (cc + EPSF) >= 0.02f);
        float score = valid ? bv : 0.0f;

        float* o = out + c * 14;
        o[0]  = 0.0f;
        o[1]  = (float)c;
        o[2]  = bx - r;
        o[3]  = by - r;
        o[4]  = bx + r;
        o[5]  = by + r;
        o[6]  = score;
        o[7]  = poses[c * 13 + 6];
        o[8]  = poses[c * 13 + 7];
        o[9]  = poses[c * 13 + 8];
        o[10] = poses[c * 13 + 9];
        o[11] = (bx - ppx) * z / fx;
        o[12] = (by - ppy) * z / fy;
        o[13] = z;

        g_clsCnt[c] = 0;                 // reset for next graph replay
        g_zsum[c]   = 0.0f;
    }
    for (int i = t; i < NQ * NR; i += THR) g_accP[i] = 0ULL;
    __threadfence();
    if (t == 0) { g_phase1 = 0; g_phase2 = 0; }
}

// ---------------- launch ------------------------------------------------------
extern "C" void kernel_launch(void* const* d_in, const int* in_sizes, int n_in,
                              void* d_out, int out_size) {
    const int*   label   = (const int*)  d_in[0];   // (1,240,320) int32
    const float* vp      = (const float*)d_in[1];   // (1,66,240,320) f32
    const float* extents = (const float*)d_in[2];   // (22,3) f32
    const float* poses   = (const float*)d_in[3];   // (22,13) f32
    const float* mdata   = (const float*)d_in[4];   // (1,9) f32
    float*       out     = (float*)d_out;           // (1,22,14) f32

    k_all<<<BLKS, THR>>>(label, vp, extents, poses, mdata, out);
}